// round 1
// baseline (speedup 1.0000x reference)
#include <cuda_runtime.h>
#include <math.h>

// Problem constants
#define N_ROWS 32768     // 32*32*32 flattened rows
#define DIM    256       // embedding dim
#define KCODES 1024      // codebook entries
#define M_OUT  (N_ROWS * DIM)   // ste element count = 8388608

// Tiling
#define BN 64            // rows per block
#define BK 128           // codes per k-chunk
#define BD 16            // d-slice per B-tile load
#define AS_STRIDE 68     // padded row stride for transposed A tile (multiple of 4 floats)

// Scratch in device globals (no allocations allowed)
__device__ __align__(16) float g_cbT[KCODES * DIM];   // codebook transposed: [k][d]
__device__ __align__(16) float g_cnorm[KCODES];       // |c_k|^2
__device__ int    g_counts[KCODES];
__device__ double g_sqsum;

// ---------------------------------------------------------------------------
// Prep: cnorm, codebook transpose, zero accumulators (runs every launch so
// graph replays are deterministic).
// ---------------------------------------------------------------------------
__global__ void vq_prep(const float* __restrict__ cb) {
    int k = blockIdx.x * 256 + threadIdx.x;   // 0..1023
    float s = 0.0f;
    #pragma unroll 8
    for (int d = 0; d < DIM; d++) {
        float v = cb[d * KCODES + k];         // coalesced across k
        s += v * v;
        g_cbT[k * DIM + d] = v;
    }
    g_cnorm[k] = s;
    g_counts[k] = 0;
    if (k == 0) g_sqsum = 0.0;
}

// ---------------------------------------------------------------------------
// Main: fused distance-GEMM + argmin + quantized gather + ste write + MSE +
// histogram. One block per 64 rows.
// ---------------------------------------------------------------------------
__global__ __launch_bounds__(256, 2)
void vq_main(const float* __restrict__ x, const float* __restrict__ cb,
             float* __restrict__ out) {
    extern __shared__ float smem[];
    float* As = smem;                              // [DIM][AS_STRIDE] transposed: As[d][row]
    float* Bs = As + DIM * AS_STRIDE;              // [BD][BK]
    int*   s_idx = (int*)(Bs + BD * BK);           // [BN]
    float* s_red = (float*)(s_idx + BN);           // [8]

    const int tid = threadIdx.x;
    const int tx  = tid & 31;       // lane
    const int ty  = tid >> 5;       // warp 0..7 -> owns rows ty*8 .. ty*8+7
    const int rowbase = blockIdx.x * BN;

    // ---- Load A tile (64 x 256) transposed into SMEM ----
    {
        const float4* xg = (const float4*)(x + (size_t)rowbase * DIM);
        #pragma unroll
        for (int i = 0; i < 16; i++) {
            int f  = tid + i * 256;       // float4 index within tile (0..4095)
            int r  = f >> 6;              // 64 float4 per row
            int c4 = f & 63;
            float4 v = xg[f];
            int d = c4 * 4;
            As[(d + 0) * AS_STRIDE + r] = v.x;
            As[(d + 1) * AS_STRIDE + r] = v.y;
            As[(d + 2) * AS_STRIDE + r] = v.z;
            As[(d + 3) * AS_STRIDE + r] = v.w;
        }
    }
    __syncthreads();

    float bval[8];
    int   bidx[8];
    #pragma unroll
    for (int i = 0; i < 8; i++) { bval[i] = 3.4e38f; bidx[i] = 0; }

    // ---- k-chunk loop ----
    for (int k0 = 0; k0 < KCODES; k0 += BK) {
        float acc[8][4];
        #pragma unroll
        for (int i = 0; i < 8; i++)
            #pragma unroll
            for (int j = 0; j < 4; j++) acc[i][j] = 0.0f;

        for (int d0 = 0; d0 < DIM; d0 += BD) {
            // load B tile: codebook[(d0..d0+BD), k0..k0+BK]
            #pragma unroll
            for (int i = 0; i < 2; i++) {
                int f  = tid + i * 256;   // float4 idx 0..511
                int dd = f >> 5;          // 32 float4 per row
                int c4 = f & 31;
                float4 v = *(const float4*)(cb + (size_t)(d0 + dd) * KCODES + k0 + c4 * 4);
                *(float4*)(&Bs[dd * BK + c4 * 4]) = v;
            }
            __syncthreads();

            #pragma unroll
            for (int dd = 0; dd < BD; dd++) {
                const float* arow = &As[(d0 + dd) * AS_STRIDE + (ty << 3)];
                float4 a0 = *(const float4*)(arow);        // warp-uniform broadcast
                float4 a1 = *(const float4*)(arow + 4);    // warp-uniform broadcast
                float4 bq = *(const float4*)(&Bs[dd * BK + (tx << 2)]);
                float av[8] = {a0.x, a0.y, a0.z, a0.w, a1.x, a1.y, a1.z, a1.w};
                float bv4[4] = {bq.x, bq.y, bq.z, bq.w};
                #pragma unroll
                for (int i = 0; i < 8; i++)
                    #pragma unroll
                    for (int j = 0; j < 4; j++)
                        acc[i][j] = fmaf(av[i], bv4[j], acc[i][j]);
            }
            __syncthreads();
        }

        // ---- argmin over this chunk (distance = |c|^2 - 2 x.c ; |x|^2 const) ----
        float4 cn = *(const float4*)(&g_cnorm[k0 + (tx << 2)]);
        float cnv[4] = {cn.x, cn.y, cn.z, cn.w};
        #pragma unroll
        for (int i = 0; i < 8; i++) {
            int kk = k0 + (tx << 2);
            float bv = cnv[0] - 2.0f * acc[i][0];
            int   bk = kk;
            #pragma unroll
            for (int j = 1; j < 4; j++) {
                float v = cnv[j] - 2.0f * acc[i][j];
                if (v < bv) { bv = v; bk = kk + j; }     // strict < keeps first index
            }
            // warp butterfly reduce (min, first-index tie-break)
            #pragma unroll
            for (int off = 16; off; off >>= 1) {
                float ov = __shfl_xor_sync(0xffffffffu, bv, off);
                int   ok = __shfl_xor_sync(0xffffffffu, bk, off);
                if (ov < bv || (ov == bv && ok < bk)) { bv = ov; bk = ok; }
            }
            if (bv < bval[i]) { bval[i] = bv; bidx[i] = bk; }
        }
    }

    // ---- publish per-row best indices ----
    if (tx == 0) {
        #pragma unroll
        for (int i = 0; i < 8; i++) s_idx[(ty << 3) + i] = bidx[i];
    }
    __syncthreads();

    // histogram
    if (tid < BN) atomicAdd(&g_counts[s_idx[tid]], 1);

    // ---- epilogue: gather quantized rows, write ste, accumulate MSE ----
    float sq = 0.0f;
    const int d = tid;   // each thread owns one dim column (0..255)
    for (int r = 0; r < BN; r++) {
        int kb = s_idx[r];
        float q  = g_cbT[kb * DIM + d];            // coalesced (transposed codebook)
        float xv = As[d * AS_STRIDE + r];
        float df = q - xv;
        sq = fmaf(df, df, sq);
        out[(size_t)(rowbase + r) * DIM + d] = xv + df;   // ste = x + (q - x)
    }

    // block-reduce sq -> double atomic
    #pragma unroll
    for (int off = 16; off; off >>= 1) sq += __shfl_xor_sync(0xffffffffu, sq, off);
    if (tx == 0) s_red[ty] = sq;
    __syncthreads();
    if (tid == 0) {
        float t = 0.0f;
        #pragma unroll
        for (int i = 0; i < 8; i++) t += s_red[i];
        atomicAdd(&g_sqsum, (double)t);
    }
}

// ---------------------------------------------------------------------------
// Finalize: perplexity + losses
// ---------------------------------------------------------------------------
__global__ void vq_final(float* __restrict__ out) {
    __shared__ float red[32];
    int k = threadIdx.x;                 // 1024 threads
    float c = (float)g_counts[k];
    float p = c * (1.0f / (float)N_ROWS);
    float t = -p * logf(p + 1e-10f);
    #pragma unroll
    for (int off = 16; off; off >>= 1) t += __shfl_xor_sync(0xffffffffu, t, off);
    if ((k & 31) == 0) red[k >> 5] = t;
    __syncthreads();
    if (k < 32) {
        float v = red[k];
        #pragma unroll
        for (int off = 16; off; off >>= 1) v += __shfl_xor_sync(0xffffffffu, v, off);
        if (k == 0) {
            float perplexity = expf(v);
            float loss = (float)(g_sqsum / (double)M_OUT);
            out[M_OUT + 0] = perplexity;
            out[M_OUT + 1] = loss;           // codebook loss
            out[M_OUT + 2] = 0.25f * loss;   // commitment loss
        }
    }
}

// ---------------------------------------------------------------------------
// kernel_launch
// ---------------------------------------------------------------------------
extern "C" void kernel_launch(void* const* d_in, const int* in_sizes, int n_in,
                              void* d_out, int out_size) {
    const float* x  = (const float*)d_in[0];   // inputs (32,32,32,256) f32
    const float* cb = (const float*)d_in[1];   // codebook (256,1024) f32
    float* out = (float*)d_out;

    const int smem_bytes = DIM * AS_STRIDE * sizeof(float)   // As (transposed tile)
                         + BD * BK * sizeof(float)           // Bs
                         + BN * sizeof(int)                  // s_idx
                         + 8 * sizeof(float);                // s_red

    cudaFuncSetAttribute(vq_main, cudaFuncAttributeMaxDynamicSharedMemorySize, smem_bytes);

    vq_prep<<<KCODES / 256, 256>>>(cb);
    vq_main<<<N_ROWS / BN, 256, smem_bytes>>>(x, cb, out);
    vq_final<<<1, KCODES>>>(out);
}